// round 8
// baseline (speedup 1.0000x reference)
#include <cuda_runtime.h>

#define U 128
#define ROW_IN   (4 * U)   // 512 floats per x1 row
#define ROW_OUT  (11 * U)  // 1408 floats per output row
#define NWARPS   8
#define NTHREADS (NWARPS * 32)     // 256
#define GRID     608               // 152 SMs * 4 blocks -> single persistent wave

// Per-warp smem: 128 floats input stage + 288 floats output stage
#define WIN_F   128
#define WOUT_F  288
#define WSMEM_F (WIN_F + WOUT_F)   // 416 floats

__global__ __launch_bounds__(NTHREADS, 4)
void ChannelWiseTensorProduct_85779086836293_kernel(
    const float* __restrict__ x1,
    const float* __restrict__ x2,
    const float* __restrict__ w,
    float* __restrict__ out,
    int B)
{
    __shared__ float smem[NWARPS * WSMEM_F];

    const int t    = threadIdx.x;
    const int wid  = t >> 5;
    const int lane = t & 31;
    const int rowInBlk = wid >> 2;    // 0..1  (2 rows per block per iteration)
    const int wr       = wid & 3;     // warp-in-row, 0..3

    float* swin  = smem + wid * WSMEM_F;
    float* swout = swin + WIN_F;

    // Channel owned by this lane and its loop-invariant weights
    const int u = 32 * wr + lane;
    const float w0 = w[u];
    const float w1 = w[U + u];
    const float w2 = w[2 * U + u];
    const float w3 = w[3 * U + u];
    const float w4 = w[4 * U + u];

    const float INV_SQRT3 = 0.57735026918962576451f;
    const float INV_SQRT2 = 0.70710678118654752440f;

    // Input gather index: one float4 per lane covers this warp's 128 input floats
    const int gidx = (lane < 8) ? (8 * wr + lane) : (32 + 24 * wr + (lane - 8));

    // Flush mapping (loop-invariant): 72 float4 per warp across 3 segments
    const int i0 = lane;              // seg 0|1
    const int s0seg = i0 / 24;
    const int g0 = ((s0seg == 0) ? 32 : 128) + 24 * wr + (i0 - s0seg * 24);
    const int i1 = lane + 32;         // seg 1|2
    const int s1seg = i1 / 24;
    const int g1 = ((s1seg == 1) ? 128 : 256) + 24 * wr + (i1 - s1seg * 24);
    const int i2 = lane + 64;         // seg 2 (lanes 0..7)
    const int g2 = 256 + 24 * wr + (i2 - 48);

    const int stride = GRID * 2;
    int b = blockIdx.x * 2 + rowInBlk;

    // ---- Initial prefetch (registers) ----
    float4 rin;
    float yv;
    {
        const int bb = min(b, B - 1);
        rin = __ldcs(&reinterpret_cast<const float4*>(x1 + (size_t)bb * ROW_IN)[gidx]);
        yv  = (lane < 4) ? __ldcs(&x2[(size_t)bb * 4 + lane]) : 0.0f;
    }

    while (b < B) {
        // Stage prefetched input
        reinterpret_cast<float4*>(swin)[lane] = rin;
        const float y0  = __shfl_sync(0xffffffffu, yv, 0);
        const float y10 = __shfl_sync(0xffffffffu, yv, 1);
        const float y11 = __shfl_sync(0xffffffffu, yv, 2);
        const float y12 = __shfl_sync(0xffffffffu, yv, 3);
        __syncwarp();

        const float s0 = swin[lane];
        const float a0 = swin[32 + 3 * lane + 0];
        const float a1 = swin[32 + 3 * lane + 1];
        const float a2 = swin[32 + 3 * lane + 2];

        // ---- Prefetch next row while this row computes/stores ----
        const int bn = b + stride;
        {
            const int bb = min(bn, B - 1);
            rin = __ldcs(&reinterpret_cast<const float4*>(x1 + (size_t)bb * ROW_IN)[gidx]);
            yv  = (lane < 4) ? __ldcs(&x2[(size_t)bb * 4 + lane]) : 0.0f;
        }

        float* orow = out + (size_t)b * ROW_OUT;

        // Direct coalesced scalar stores (one 128B line per warp each)
        __stcs(&orow[u], w0 * s0 * y0);
        __stcs(&orow[7 * U + u], w3 * (a0 * y10 + a1 * y11 + a2 * y12) * INV_SQRT3);

        // Stage the three 3-vector segments (96 floats each)
        const float ws0 = w1 * s0;
        swout[3 * lane + 0] = ws0 * y10;
        swout[3 * lane + 1] = ws0 * y11;
        swout[3 * lane + 2] = ws0 * y12;

        const float wy = w2 * y0;
        swout[96 + 3 * lane + 0] = wy * a0;
        swout[96 + 3 * lane + 1] = wy * a1;
        swout[96 + 3 * lane + 2] = wy * a2;

        const float c0 = a1 * y12 - a2 * y11;
        const float c1 = a2 * y10 - a0 * y12;
        const float c2 = a0 * y11 - a1 * y10;
        const float w4s = w4 * INV_SQRT2;
        swout[192 + 3 * lane + 0] = w4s * c0;
        swout[192 + 3 * lane + 1] = w4s * c1;
        swout[192 + 3 * lane + 2] = w4s * c2;

        __syncwarp();

        // Flush: 72 float4 per warp, streaming stores
        float4* ov = reinterpret_cast<float4*>(orow);
        const float4* sv = reinterpret_cast<const float4*>(swout);
        __stcs(&ov[g0], sv[i0]);
        __stcs(&ov[g1], sv[i1]);
        if (lane < 8) __stcs(&ov[g2], sv[i2]);

        b = bn;
    }
}

extern "C" void kernel_launch(void* const* d_in, const int* in_sizes, int n_in,
                              void* d_out, int out_size) {
    const float* x1 = (const float*)d_in[0];
    const float* x2 = (const float*)d_in[1];
    const float* w  = (const float*)d_in[2];
    float* out = (float*)d_out;

    const int B = in_sizes[0] / ROW_IN;  // 65536
    ChannelWiseTensorProduct_85779086836293_kernel<<<GRID, NTHREADS>>>(x1, x2, w, out, B);
}

// round 9
// speedup vs baseline: 1.0939x; 1.0939x over previous
#include <cuda_runtime.h>

#define U 128
#define ROW_IN  (4 * U)   // 512 floats per x1 row
#define ROW_OUT (11 * U)  // 1408 floats per output row

__global__ __launch_bounds__(128, 16)
void ChannelWiseTensorProduct_85779086836293_kernel(
    const float* __restrict__ x1,
    const float* __restrict__ x2,
    const float* __restrict__ w,
    float* __restrict__ out)
{
    __shared__ float sin_row[ROW_IN];
    __shared__ float sout_vec[3 * 3 * U];   // staged o1 | o2 | o4 (384 floats each)
    __shared__ float sy[4];

    const int b = blockIdx.x;
    const int t = threadIdx.x;

    // --- Load x1 row (512 floats), streaming (no reuse) ---
    const float4* x1v = reinterpret_cast<const float4*>(x1 + (size_t)b * ROW_IN);
    reinterpret_cast<float4*>(sin_row)[t] = __ldcs(&x1v[t]);

    // --- Load x2 row (4 floats), streaming ---
    if (t < 4) sy[t] = __ldcs(&x2[(size_t)b * 4 + t]);

    __syncthreads();

    const float y0  = sy[0];
    const float y10 = sy[1];
    const float y11 = sy[2];
    const float y12 = sy[3];

    // Per-channel inputs: s0[u], s1[u][0..2]
    const float s0 = sin_row[t];
    const float a0 = sin_row[U + 3 * t + 0];
    const float a1 = sin_row[U + 3 * t + 1];
    const float a2 = sin_row[U + 3 * t + 2];

    // Weights (broadcast across blocks; keep cached)
    const float w0 = w[t];
    const float w1 = w[U + t];
    const float w2 = w[2 * U + t];
    const float w3 = w[3 * U + t];
    const float w4 = w[4 * U + t];

    const float INV_SQRT3 = 0.57735026918962576451f;
    const float INV_SQRT2 = 0.70710678118654752440f;

    float* orow = out + (size_t)b * ROW_OUT;

    // o0[u] = w0 * s0 * y0  — direct coalesced scalar store (full lines/warp)
    __stcs(&orow[t], w0 * s0 * y0);

    // o3[u] = w3 * dot(s1[u], y1) / sqrt(3) — direct coalesced scalar store
    __stcs(&orow[7 * U + t], w3 * (a0 * y10 + a1 * y11 + a2 * y12) * INV_SQRT3);

    // o1[u,j] = w1 * s0 * y1[j]  -> staged at sout_vec[0..384)
    const float ws0 = w1 * s0;
    sout_vec[3 * t + 0] = ws0 * y10;
    sout_vec[3 * t + 1] = ws0 * y11;
    sout_vec[3 * t + 2] = ws0 * y12;

    // o2[u,i] = w2 * y0 * s1[u,i] -> staged at sout_vec[384..768)
    const float wy = w2 * y0;
    sout_vec[3 * U + 3 * t + 0] = wy * a0;
    sout_vec[3 * U + 3 * t + 1] = wy * a1;
    sout_vec[3 * U + 3 * t + 2] = wy * a2;

    // o4[u,k] = w4 * cross(s1[u], y1)[k] / sqrt(2) -> staged at sout_vec[768..1152)
    const float c0 = a1 * y12 - a2 * y11;
    const float c1 = a2 * y10 - a0 * y12;
    const float c2 = a0 * y11 - a1 * y10;
    const float w4s = w4 * INV_SQRT2;
    sout_vec[6 * U + 3 * t + 0] = w4s * c0;
    sout_vec[6 * U + 3 * t + 1] = w4s * c1;
    sout_vec[6 * U + 3 * t + 2] = w4s * c2;

    __syncthreads();

    // --- Flush the three staged 3-vector segments (288 float4s), streaming stores.
    // Staged float4 index i in [0,288): segment = i/96, offset-in-segment = i%96.
    // Global float4 bases: o1 -> 32 (float 128), o2 -> 128 (float 512), o4 -> 256 (float 1024).
    float4* ov = reinterpret_cast<float4*>(orow);
    const float4* sv = reinterpret_cast<const float4*>(sout_vec);

    {
        // i = t  (segment 0 for t<96, segment 1 for t>=96)
        const int i = t;
        const int seg = i / 96;
        const int off = i - seg * 96;
        const int gbase = (seg == 0) ? 32 : 128;
        __stcs(&ov[gbase + off], sv[i]);
    }
    {
        // i = t + 128 (segment 1 for t<64, segment 2 for t>=64)
        const int i = t + 128;
        const int seg = i / 96;
        const int off = i - seg * 96;
        const int gbase = (seg == 1) ? 128 : 256;
        __stcs(&ov[gbase + off], sv[i]);
    }
    if (t < 32) {
        // i = t + 256 (segment 2)
        const int i = t + 256;
        const int off = i - 192;
        __stcs(&ov[256 + off], sv[i]);
    }
}

extern "C" void kernel_launch(void* const* d_in, const int* in_sizes, int n_in,
                              void* d_out, int out_size) {
    const float* x1 = (const float*)d_in[0];
    const float* x2 = (const float*)d_in[1];
    const float* w  = (const float*)d_in[2];
    float* out = (float*)d_out;

    const int B = in_sizes[0] / ROW_IN;  // 65536
    ChannelWiseTensorProduct_85779086836293_kernel<<<B, 128>>>(x1, x2, w, out);
}

// round 10
// speedup vs baseline: 1.0997x; 1.0054x over previous
#include <cuda_runtime.h>
#include <cstdint>

#define U 128
#define ROW_IN  (4 * U)   // 512 floats per x1 row
#define ROW_OUT (11 * U)  // 1408 floats = 5632 bytes per output row

__global__ __launch_bounds__(128, 8)
void ChannelWiseTensorProduct_85779086836293_kernel(
    const float* __restrict__ x1,
    const float* __restrict__ x2,
    const float* __restrict__ w,
    float* __restrict__ out)
{
    __shared__ __align__(16) float sout[ROW_OUT];   // full staged output row
    __shared__ __align__(16) float sin_row[ROW_IN];
    __shared__ float sy[4];

    const int b = blockIdx.x;
    const int t = threadIdx.x;

    // --- Load x1 row (512 floats), streaming, fully coalesced float4 ---
    const float4* x1v = reinterpret_cast<const float4*>(x1 + (size_t)b * ROW_IN);
    reinterpret_cast<float4*>(sin_row)[t] = __ldcs(&x1v[t]);

    // --- Load x2 row (4 floats) ---
    if (t < 4) sy[t] = __ldcs(&x2[(size_t)b * 4 + t]);

    __syncthreads();

    const float y0  = sy[0];
    const float y10 = sy[1];
    const float y11 = sy[2];
    const float y12 = sy[3];

    const float s0 = sin_row[t];
    const float a0 = sin_row[U + 3 * t + 0];
    const float a1 = sin_row[U + 3 * t + 1];
    const float a2 = sin_row[U + 3 * t + 2];

    const float w0 = w[t];
    const float w1 = w[U + t];
    const float w2 = w[2 * U + t];
    const float w3 = w[3 * U + t];
    const float w4 = w[4 * U + t];

    const float INV_SQRT3 = 0.57735026918962576451f;
    const float INV_SQRT2 = 0.70710678118654752440f;

    // --- Stage ALL outputs in smem in final row layout ---
    // o0[u]
    sout[t] = w0 * s0 * y0;

    // o1[u,j] at floats [U .. 4U)
    const float ws0 = w1 * s0;
    sout[U + 3 * t + 0] = ws0 * y10;
    sout[U + 3 * t + 1] = ws0 * y11;
    sout[U + 3 * t + 2] = ws0 * y12;

    // o2[u,i] at floats [4U .. 7U)
    const float wy = w2 * y0;
    sout[4 * U + 3 * t + 0] = wy * a0;
    sout[4 * U + 3 * t + 1] = wy * a1;
    sout[4 * U + 3 * t + 2] = wy * a2;

    // o3[u] at floats [7U .. 8U)
    sout[7 * U + t] = w3 * (a0 * y10 + a1 * y11 + a2 * y12) * INV_SQRT3;

    // o4[u,k] at floats [8U .. 11U)
    const float c0 = a1 * y12 - a2 * y11;
    const float c1 = a2 * y10 - a0 * y12;
    const float c2 = a0 * y11 - a1 * y10;
    const float w4s = w4 * INV_SQRT2;
    sout[8 * U + 3 * t + 0] = w4s * c0;
    sout[8 * U + 3 * t + 1] = w4s * c1;
    sout[8 * U + 3 * t + 2] = w4s * c2;

    __syncthreads();

    // --- Single bulk async store: 5632 contiguous bytes SMEM -> GMEM ---
    if (t == 0) {
        // Order the generic-proxy smem stores above before the async-proxy read.
        asm volatile("fence.proxy.async.shared::cta;" ::: "memory");

        uint32_t saddr;
        asm("{ .reg .u64 tmp; cvta.to.shared.u64 tmp, %1; cvt.u32.u64 %0, tmp; }"
            : "=r"(saddr) : "l"(static_cast<const void*>(sout)));

        const float* gdst = out + (size_t)b * ROW_OUT;
        asm volatile(
            "cp.async.bulk.global.shared::cta.bulk_group [%0], [%1], %2;"
            :: "l"(gdst), "r"(saddr), "n"(ROW_OUT * 4)
            : "memory");
        asm volatile("cp.async.bulk.commit_group;" ::: "memory");
        asm volatile("cp.async.bulk.wait_group 0;" ::: "memory");
    }
}

extern "C" void kernel_launch(void* const* d_in, const int* in_sizes, int n_in,
                              void* d_out, int out_size) {
    const float* x1 = (const float*)d_in[0];
    const float* x2 = (const float*)d_in[1];
    const float* w  = (const float*)d_in[2];
    float* out = (float*)d_out;

    const int B = in_sizes[0] / ROW_IN;  // 65536
    ChannelWiseTensorProduct_85779086836293_kernel<<<B, 128>>>(x1, x2, w, out);
}